// round 1
// baseline (speedup 1.0000x reference)
#include <cuda_runtime.h>

// SMorph: out[b,c,oy,ox] = sum_k (x_p + f_k) exp(a(x_p+f_k)) / sum_k exp(a(x_p+f_k))
// Factored: G=exp(a*x), H=x*G, E_k=exp(a*f_k), F_k=f_k*E_k
//   num = sum_k E_k*H(p_k) + F_k*G(p_k);  den = sum_k E_k*G(p_k)
// => three 7x7 correlations over smem-resident G/H planes.

namespace {
constexpr int BATCH = 8;
constexpr int HH = 192, WW = 192;
constexpr int CO = 8;
constexpr int KH = 7, KW = 7;
constexpr int HO = 186, WO = 186;

constexpr int TILE_X = 64;           // output tile width
constexpr int TILE_Y = 16;           // output tile height
constexpr int ITX = TILE_X + KW - 1; // 70 input cols
constexpr int ITY = TILE_Y + KH - 1; // 22 input rows
constexpr int PITCH = ITX + 1;       // 71 (odd) -> staggered banks
}

__global__ __launch_bounds__(256, 4)
void smorph_kernel(const float* __restrict__ x,
                   const float* __restrict__ filt,
                   const float* __restrict__ alpha,
                   float* __restrict__ out)
{
    __shared__ float sG[ITY * PITCH];
    __shared__ float sH[ITY * PITCH];
    __shared__ float sE[KH * KW];
    __shared__ float sF[KH * KW];

    const int bc = blockIdx.z;          // b*8 + c
    const int c  = bc & 7;
    const int b  = bc >> 3;
    const int tid = threadIdx.y * 16 + threadIdx.x;

    const float a = alpha[c];

    // Per-cout tap weights: E = exp(a*f), F = f*E
    if (tid < KH * KW) {
        float f = filt[c * (KH * KW) + tid];
        float e = __expf(a * f);
        sE[tid] = e;
        sF[tid] = f * e;
    }

    const int gx0 = blockIdx.x * TILE_X;
    const int gy0 = blockIdx.y * TILE_Y;
    const float* xb = x + b * (HH * WW);

    // Cooperative tile load: compute G = exp(a*x), H = x*G on the fly.
    for (int i = tid; i < ITY * ITX; i += 256) {
        int iy = i / ITX;
        int ix = i - iy * ITX;
        int gy = gy0 + iy;
        int gx = gx0 + ix;
        float v = (gy < HH && gx < WW) ? xb[gy * WW + gx] : 0.0f;
        float g = __expf(a * v);
        sG[iy * PITCH + ix] = g;
        sH[iy * PITCH + ix] = v * g;
    }
    __syncthreads();

    // Each thread computes 4 horizontally-adjacent outputs.
    const int lx = threadIdx.x * 4;   // 0..60
    const int ly = threadIdx.y;       // 0..15

    float num0 = 0.f, num1 = 0.f, num2 = 0.f, num3 = 0.f;
    float den0 = 0.f, den1 = 0.f, den2 = 0.f, den3 = 0.f;

    #pragma unroll
    for (int ky = 0; ky < KH; ky++) {
        const float* gr = &sG[(ly + ky) * PITCH + lx];
        const float* hr = &sH[(ly + ky) * PITCH + lx];
        float g[KW + 3], h[KW + 3];
        #pragma unroll
        for (int i = 0; i < KW + 3; i++) {
            g[i] = gr[i];
            h[i] = hr[i];
        }
        #pragma unroll
        for (int kx = 0; kx < KW; kx++) {
            const float E = sE[ky * KW + kx];   // uniform broadcast LDS
            const float F = sF[ky * KW + kx];
            num0 = fmaf(E, h[kx + 0], fmaf(F, g[kx + 0], num0));
            den0 = fmaf(E, g[kx + 0], den0);
            num1 = fmaf(E, h[kx + 1], fmaf(F, g[kx + 1], num1));
            den1 = fmaf(E, g[kx + 1], den1);
            num2 = fmaf(E, h[kx + 2], fmaf(F, g[kx + 2], num2));
            den2 = fmaf(E, g[kx + 2], den2);
            num3 = fmaf(E, h[kx + 3], fmaf(F, g[kx + 3], num3));
            den3 = fmaf(E, g[kx + 3], den3);
        }
    }

    const int oy = gy0 + ly;
    const int ox = gx0 + lx;
    if (oy < HO) {
        float* orow = out + ((long)bc * HO + oy) * WO;
        if (ox + 0 < WO) orow[ox + 0] = __fdividef(num0, den0);
        if (ox + 1 < WO) orow[ox + 1] = __fdividef(num1, den1);
        if (ox + 2 < WO) orow[ox + 2] = __fdividef(num2, den2);
        if (ox + 3 < WO) orow[ox + 3] = __fdividef(num3, den3);
    }
}

extern "C" void kernel_launch(void* const* d_in, const int* in_sizes, int n_in,
                              void* d_out, int out_size) {
    const float* x     = (const float*)d_in[0];   // (8,1,192,192)
    const float* filt  = (const float*)d_in[1];   // (8,1,7,7)
    const float* alpha = (const float*)d_in[2];   // (8,1)
    float* out = (float*)d_out;                   // (8,8,186,186)

    dim3 block(16, 16);
    dim3 grid((WO + TILE_X - 1) / TILE_X,   // 3
              (HO + TILE_Y - 1) / TILE_Y,   // 12
              BATCH * CO);                  // 64
    smorph_kernel<<<grid, block>>>(x, filt, alpha, out);
}